// round 3
// baseline (speedup 1.0000x reference)
#include <cuda_runtime.h>
#include <math.h>

// Problem constants
#define Bsz 4
#define Ssz 4096
#define Hn  8
#define DIc 128
#define DOc 128
#define Tsz (Bsz*Ssz)        // 16384 tokens
#define K1c 256              // 2*DI
#define N1c 384              // 3*DO
#define N2c 128
#define NC  64               // scan chunks
#define LC  (Ssz/NC)         // 64 steps per chunk
#define EPSf 1e-6f

// ---------------- static scratch (device globals; no allocation) -------------
__device__ float buf_csum[(size_t)Tsz*Hn*DIc];        // exclusive cumsum    64MB
__device__ float buf_x   [(size_t)Tsz*Hn*K1c];        // [input, ln(csum)]  128MB
__device__ float buf_h3  [(size_t)Tsz*Hn*N1c];        // gemm1 out          192MB
__device__ float buf_fg  [(size_t)Tsz*Hn*DOc];        // sigmoid(fgate)      64MB
__device__ float buf_igh [(size_t)Tsz*Hn*DOc];        // sig(i)*relu(h)      64MB
__device__ float buf_x2  [(size_t)Tsz*Hn*K1c];        // [input, cell]      128MB
__device__ float buf_og  [(size_t)Tsz*Hn*DOc];        // gemm2 out           64MB
__device__ float buf_chunk[Bsz*NC*Hn*DIc];            // cumsum chunk sums
__device__ float buf_Fc  [Bsz*NC*Hn*DOc];
__device__ float buf_Ic  [Bsz*NC*Hn*DOc];
__device__ float buf_cst [Bsz*NC*Hn*DOc];

// ---------------- helpers ----------------------------------------------------
__device__ __forceinline__ void block_reduce2(float& s, float& ss) {
    __shared__ float shs[32], shss[32];
    #pragma unroll
    for (int o = 16; o > 0; o >>= 1) {
        s  += __shfl_down_sync(0xffffffffu, s,  o);
        ss += __shfl_down_sync(0xffffffffu, ss, o);
    }
    int lane = threadIdx.x & 31, w = threadIdx.x >> 5, nw = blockDim.x >> 5;
    if (lane == 0) { shs[w] = s; shss[w] = ss; }
    __syncthreads();
    if (w == 0) {
        s  = (lane < nw) ? shs[lane]  : 0.f;
        ss = (lane < nw) ? shss[lane] : 0.f;
        #pragma unroll
        for (int o = 16; o > 0; o >>= 1) {
            s  += __shfl_down_sync(0xffffffffu, s,  o);
            ss += __shfl_down_sync(0xffffffffu, ss, o);
        }
        if (lane == 0) { shs[0] = s; shss[0] = ss; }
    }
    __syncthreads();
    s = shs[0]; ss = shss[0];
}

__device__ __forceinline__ float sigm(float x) { return 1.f / (1.f + expf(-x)); }

// ---------------- K1: exclusive cumsum over S (chunked) ----------------------
__global__ void k_chunksum(const float* __restrict__ in) {
    int blk = blockIdx.x;
    int n = blk % Hn; int c = (blk / Hn) % NC; int b = blk / (Hn * NC);
    int d = threadIdx.x;
    size_t base = ((size_t)(b * Ssz + c * LC) * Hn + n) * DIc + d;
    float s = 0.f;
    #pragma unroll 4
    for (int i = 0; i < LC; i++) s += in[base + (size_t)i * Hn * DIc];
    buf_chunk[((b * NC + c) * Hn + n) * DIc + d] = s;
}

__global__ void k_chunkscan() {
    int n = blockIdx.x % Hn, b = blockIdx.x / Hn;
    int d = threadIdx.x;
    float run = 0.f;
    for (int c = 0; c < NC; c++) {
        int idx = ((b * NC + c) * Hn + n) * DIc + d;
        float t = buf_chunk[idx];
        buf_chunk[idx] = run;
        run += t;
    }
}

__global__ void k_csum(const float* __restrict__ in) {
    int blk = blockIdx.x;
    int n = blk % Hn; int c = (blk / Hn) % NC; int b = blk / (Hn * NC);
    int d = threadIdx.x;
    float run = buf_chunk[((b * NC + c) * Hn + n) * DIc + d];
    size_t base = ((size_t)(b * Ssz + c * LC) * Hn + n) * DIc + d;
    for (int i = 0; i < LC; i++) {
        size_t p = base + (size_t)i * Hn * DIc;
        buf_csum[p] = run;
        run += in[p];
    }
}

// ---------------- K2: token LN of csum + assemble x = [input, ln(csum)] ------
__global__ void k_lnx(const float* __restrict__ in,
                      const float* __restrict__ gc, const float* __restrict__ bc) {
    int t = blockIdx.x;
    int tid = threadIdx.x;            // 256
    const float* cs = buf_csum + (size_t)t * (Hn * DIc);
    float s = 0.f, ss = 0.f;
    #pragma unroll
    for (int i = tid; i < Hn * DIc; i += 256) { float v = cs[i]; s += v; ss += v * v; }
    block_reduce2(s, ss);
    float mu = s * (1.f / (Hn * DIc));
    float var = ss * (1.f / (Hn * DIc)) - mu * mu;
    float rs = rsqrtf(var + EPSf);
    float* xp = buf_x + (size_t)t * (Hn * K1c);
    const float* ip = in + (size_t)t * (Hn * DIc);
    #pragma unroll
    for (int i = tid; i < Hn * DIc; i += 256) {
        int n = i >> 7, d = i & 127;
        xp[n * K1c + d]       = ip[i];
        xp[n * K1c + 128 + d] = (cs[i] - mu) * rs * gc[i] + bc[i];
    }
}

// ---------------- GEMM (128x128x8 fp32 tile, per-head batched) ---------------
// X layout: [t][head][K1c] (row stride Hn*K1c), W: [head][K][N], Y: [t][head][N]
template <int N, int WHICH>
__global__ void __launch_bounds__(256) k_gemm(const float* __restrict__ W,
                                              const float* __restrict__ bias) {
    const float* X = (WHICH == 0) ? buf_x : buf_x2;
    float*       Y = (WHICH == 0) ? buf_h3 : buf_og;
    const int n  = blockIdx.z;
    const int m0 = blockIdx.y * 128;
    const int n0 = blockIdx.x * 128;

    __shared__ float As[8][132];   // padded, stored transposed [k][m]
    __shared__ float Bs[8][128];

    const float* Xh = X + n * K1c;             // row stride Hn*K1c = 2048
    const float* Wh = W + (size_t)n * K1c * N;
    float acc[8][8];
    #pragma unroll
    for (int i = 0; i < 8; i++)
        #pragma unroll
        for (int j = 0; j < 8; j++) acc[i][j] = 0.f;

    const int tid  = threadIdx.x;
    const int aRow = tid >> 1,  aCol = (tid & 1) * 4;
    const int bRow = tid >> 5,  bCol = (tid & 31) * 4;
    const int tx   = tid & 15,  ty   = tid >> 4;

    for (int kt = 0; kt < K1c; kt += 8) {
        float4 av = *(const float4*)(Xh + (size_t)(m0 + aRow) * (Hn * K1c) + kt + aCol);
        As[aCol + 0][aRow] = av.x; As[aCol + 1][aRow] = av.y;
        As[aCol + 2][aRow] = av.z; As[aCol + 3][aRow] = av.w;
        float4 bv = *(const float4*)(Wh + (size_t)(kt + bRow) * N + n0 + bCol);
        *(float4*)(&Bs[bRow][bCol]) = bv;
        __syncthreads();
        #pragma unroll
        for (int k = 0; k < 8; k++) {
            float4 a0 = *(const float4*)(&As[k][ty * 4]);
            float4 a1 = *(const float4*)(&As[k][ty * 4 + 64]);
            float4 b0 = *(const float4*)(&Bs[k][tx * 4]);
            float4 b1 = *(const float4*)(&Bs[k][tx * 4 + 64]);
            float ra[8] = {a0.x, a0.y, a0.z, a0.w, a1.x, a1.y, a1.z, a1.w};
            float rb[8] = {b0.x, b0.y, b0.z, b0.w, b1.x, b1.y, b1.z, b1.w};
            #pragma unroll
            for (int i = 0; i < 8; i++)
                #pragma unroll
                for (int j = 0; j < 8; j++) acc[i][j] += ra[i] * rb[j];
        }
        __syncthreads();
    }

    float* Yh = Y + n * N;
    #pragma unroll
    for (int ii = 0; ii < 2; ii++) {
        #pragma unroll
        for (int i = 0; i < 4; i++) {
            int m = m0 + ii * 64 + ty * 4 + i;
            #pragma unroll
            for (int jj = 0; jj < 2; jj++) {
                int col = n0 + jj * 64 + tx * 4;
                float4 bb = *(const float4*)(bias + n * N + col);
                float4 v;
                v.x = acc[ii * 4 + i][jj * 4 + 0] + bb.x;
                v.y = acc[ii * 4 + i][jj * 4 + 1] + bb.y;
                v.z = acc[ii * 4 + i][jj * 4 + 2] + bb.z;
                v.w = acc[ii * 4 + i][jj * 4 + 3] + bb.w;
                *(float4*)(Yh + (size_t)m * Hn * N + col) = v;
            }
        }
    }
}

// ---------------- K4: token LN of h3 (3072 vals) + gates ---------------------
__global__ void k_gates(const float* __restrict__ gh, const float* __restrict__ bh) {
    int t = blockIdx.x;
    int d = threadIdx.x;              // 128
    const float* h = buf_h3 + (size_t)t * (Hn * N1c);
    float v[24];
    float s = 0.f, ss = 0.f;
    #pragma unroll
    for (int n = 0; n < Hn; n++)
        #pragma unroll
        for (int g = 0; g < 3; g++) {
            float x = h[n * N1c + g * 128 + d];
            v[n * 3 + g] = x; s += x; ss += x * x;
        }
    block_reduce2(s, ss);
    float mu  = s * (1.f / 3072.f);
    float var = ss * (1.f / 3072.f) - mu * mu;
    float rs  = rsqrtf(var + EPSf);
    #pragma unroll
    for (int n = 0; n < Hn; n++) {
        float ig = (v[n * 3 + 0] - mu) * rs * gh[(n * 3 + 0) * 128 + d] + bh[(n * 3 + 0) * 128 + d];
        float fv = (v[n * 3 + 1] - mu) * rs * gh[(n * 3 + 1) * 128 + d] + bh[(n * 3 + 1) * 128 + d];
        float hv = (v[n * 3 + 2] - mu) * rs * gh[(n * 3 + 2) * 128 + d] + bh[(n * 3 + 2) * 128 + d];
        size_t o = (size_t)t * (Hn * DOc) + n * DOc + d;
        buf_fg[o]  = sigm(fv);
        buf_igh[o] = sigm(ig) * fmaxf(hv, 0.f);
    }
}

// ---------------- K5: chunked linear-recurrence scan -------------------------
__global__ void k_scanA() {
    int blk = blockIdx.x;
    int n = blk % Hn; int c = (blk / Hn) % NC; int b = blk / (Hn * NC);
    int d = threadIdx.x;
    size_t base = ((size_t)(b * Ssz + c * LC) * Hn + n) * DOc + d;
    float F = 1.f, I = 0.f;
    #pragma unroll 4
    for (int i = 0; i < LC; i++) {
        size_t p = base + (size_t)i * Hn * DOc;
        float f = buf_fg[p], x = buf_igh[p];
        F *= f; I = f * I + x;
    }
    int ci = ((b * NC + c) * Hn + n) * DOc + d;
    buf_Fc[ci] = F; buf_Ic[ci] = I;
}

__global__ void k_scanB(const float* __restrict__ init_cx) {
    int n = blockIdx.x % Hn, b = blockIdx.x / Hn;
    int d = threadIdx.x;
    float c0 = init_cx[n * DOc + d];
    for (int c = 0; c < NC; c++) {
        int idx = ((b * NC + c) * Hn + n) * DOc + d;
        buf_cst[idx] = c0;
        c0 = buf_Fc[idx] * c0 + buf_Ic[idx];
    }
}

__global__ void k_scanC(const float* __restrict__ in) {
    int blk = blockIdx.x;
    int n = blk % Hn; int c = (blk / Hn) % NC; int b = blk / (Hn * NC);
    int d = threadIdx.x;
    float cc = buf_cst[((b * NC + c) * Hn + n) * DOc + d];
    size_t base = ((size_t)(b * Ssz + c * LC) * Hn + n) * DOc + d;
    for (int i = 0; i < LC; i++) {
        size_t p = base + (size_t)i * Hn * DOc;
        cc = buf_fg[p] * cc + buf_igh[p];
        int t = b * Ssz + c * LC + i;
        size_t xb = (size_t)t * (Hn * K1c) + n * K1c + d;
        buf_x2[xb]       = in[((size_t)t * Hn + n) * DIc + d];
        buf_x2[xb + 128] = cc;                    // cell
    }
}

// ---------------- K7: token LN of og (1024) + sigmoid * cell -----------------
__global__ void k_out(const float* __restrict__ gg, const float* __restrict__ bg,
                      float* __restrict__ out) {
    int t = blockIdx.x;
    int tid = threadIdx.x;            // 256
    const float* o = buf_og + (size_t)t * (Hn * DOc);
    float s = 0.f, ss = 0.f;
    #pragma unroll
    for (int i = tid; i < Hn * DOc; i += 256) { float v = o[i]; s += v; ss += v * v; }
    block_reduce2(s, ss);
    float mu  = s * (1.f / 1024.f);
    float var = ss * (1.f / 1024.f) - mu * mu;
    float rs  = rsqrtf(var + EPSf);
    #pragma unroll
    for (int i = tid; i < Hn * DOc; i += 256) {
        int n = i >> 7, d = i & 127;
        float v = (o[i] - mu) * rs * gg[i] + bg[i];
        float cell = buf_x2[(size_t)t * (Hn * K1c) + n * K1c + 128 + d];
        out[(size_t)t * (Hn * DOc) + i] = cell * sigm(v);
    }
}

// ---------------- launch ------------------------------------------------------
extern "C" void kernel_launch(void* const* d_in, const int* in_sizes, int n_in,
                              void* d_out, int out_size) {
    const float* heads_input = (const float*)d_in[0];
    const float* W_hid       = (const float*)d_in[1];
    const float* b_hid       = (const float*)d_in[2];
    const float* g_csum      = (const float*)d_in[3];
    const float* beta_csum   = (const float*)d_in[4];
    const float* g_hid       = (const float*)d_in[5];
    const float* beta_hid    = (const float*)d_in[6];
    const float* W_og        = (const float*)d_in[7];
    const float* b_og        = (const float*)d_in[8];
    const float* g_og        = (const float*)d_in[9];
    const float* beta_og     = (const float*)d_in[10];
    const float* init_cx     = (const float*)d_in[11];
    float* out = (float*)d_out;

    // 1) exclusive cumsum over S
    k_chunksum<<<Bsz * NC * Hn, 128>>>(heads_input);
    k_chunkscan<<<Bsz * Hn, 128>>>();
    k_csum<<<Bsz * NC * Hn, 128>>>(heads_input);
    // 2) token LN(csum) + build x
    k_lnx<<<Tsz, 256>>>(heads_input, g_csum, beta_csum);
    // 3) GEMM1: per-head (16384 x 384 x 256)
    k_gemm<N1c, 0><<<dim3(N1c / 128, Tsz / 128, Hn), 256>>>(W_hid, b_hid);
    // 4) LN + gates
    k_gates<<<Tsz, 128>>>(g_hid, beta_hid);
    // 5) cell scan (chunked)
    k_scanA<<<Bsz * NC * Hn, 128>>>();
    k_scanB<<<Bsz * Hn, 128>>>(init_cx);
    k_scanC<<<Bsz * NC * Hn, 128>>>(heads_input);
    // 6) GEMM2: per-head (16384 x 128 x 256)
    k_gemm<N2c, 1><<<dim3(N2c / 128, Tsz / 128, Hn), 256>>>(W_og, b_og);
    // 7) final LN + sigmoid*cell
    k_out<<<Tsz, 256>>>(g_og, beta_og, out);
}

// round 6
// speedup vs baseline: 1.4497x; 1.4497x over previous
#include <cuda_runtime.h>
#include <cuda_bf16.h>
#include <math.h>
#include <cstdint>

// Problem constants
#define Bsz 4
#define Ssz 4096
#define Hn  8
#define DIc 128
#define DOc 128
#define Tsz (Bsz*Ssz)        // 16384 tokens
#define K1c 256              // 2*DI
#define N1c 384              // 3*DO
#define N2c 128
#define NC  64               // scan chunks
#define LC  (Ssz/NC)         // 64 steps per chunk
#define EPSf 1e-6f

// ---------------- static scratch (device globals; no allocation) -------------
__device__ float buf_csum[(size_t)Tsz*Hn*DIc];
__device__ __align__(16) __nv_bfloat16 buf_xh [(size_t)Tsz*Hn*K1c];  // A1 hi
__device__ __align__(16) __nv_bfloat16 buf_xl [(size_t)Tsz*Hn*K1c];  // A1 lo
__device__ __align__(16) __nv_bfloat16 buf_x2h[(size_t)Tsz*Hn*K1c];  // A2 hi
__device__ __align__(16) __nv_bfloat16 buf_x2l[(size_t)Tsz*Hn*K1c];  // A2 lo
__device__ float buf_h3  [(size_t)Tsz*Hn*N1c];
__device__ float buf_fg  [(size_t)Tsz*Hn*DOc];
__device__ float buf_igh [(size_t)Tsz*Hn*DOc];
__device__ float buf_og  [(size_t)Tsz*Hn*DOc];
__device__ float buf_chunk[Bsz*NC*Hn*DIc];
__device__ float buf_Fc  [Bsz*NC*Hn*DOc];
__device__ float buf_Ic  [Bsz*NC*Hn*DOc];
__device__ float buf_cst [Bsz*NC*Hn*DOc];
// pre-split / transposed weights: [h][n][k] bf16 hi/lo
__device__ __align__(16) __nv_bfloat16 wt1_hi[(size_t)Hn*N1c*K1c];
__device__ __align__(16) __nv_bfloat16 wt1_lo[(size_t)Hn*N1c*K1c];
__device__ __align__(16) __nv_bfloat16 wt2_hi[(size_t)Hn*N2c*K1c];
__device__ __align__(16) __nv_bfloat16 wt2_lo[(size_t)Hn*N2c*K1c];

// ---------------- PTX helpers -------------------------------------------------
__device__ __forceinline__ uint32_t smem_u32(const void* p) {
    uint32_t a;
    asm("{ .reg .u64 t; cvta.to.shared.u64 t, %1; cvt.u32.u64 %0, t; }" : "=r"(a) : "l"(p));
    return a;
}
#define CPA16(sm_addr, gm_ptr) \
    asm volatile("cp.async.cg.shared.global [%0], [%1], 16;" \
                 :: "r"(sm_addr), "l"(gm_ptr) : "memory")
#define CPA_COMMIT asm volatile("cp.async.commit_group;" ::: "memory")
#define CPA_WAIT0  asm volatile("cp.async.wait_group 0;"  ::: "memory")

#define LDSM_X4(r0,r1,r2,r3,addr) \
    asm volatile("ldmatrix.sync.aligned.m8n8.x4.shared.b16 {%0,%1,%2,%3},[%4];" \
                 : "=r"(r0),"=r"(r1),"=r"(r2),"=r"(r3) : "r"(addr))

#define MMA16816(d, a, b) \
    asm volatile("mma.sync.aligned.m16n8k16.row.col.f32.bf16.bf16.f32 " \
                 "{%0,%1,%2,%3},{%4,%5,%6,%7},{%8,%9},{%0,%1,%2,%3};" \
                 : "+f"((d)[0]),"+f"((d)[1]),"+f"((d)[2]),"+f"((d)[3]) \
                 : "r"((a)[0]),"r"((a)[1]),"r"((a)[2]),"r"((a)[3]), \
                   "r"((b)[0]),"r"((b)[1]))

__device__ __forceinline__ void bsplit(float v, __nv_bfloat16& hi, __nv_bfloat16& lo) {
    hi = __float2bfloat16_rn(v);
    lo = __float2bfloat16_rn(v - __bfloat162float(hi));
}

// ---------------- helpers ----------------------------------------------------
__device__ __forceinline__ void block_reduce2(float& s, float& ss) {
    __shared__ float shs[32], shss[32];
    #pragma unroll
    for (int o = 16; o > 0; o >>= 1) {
        s  += __shfl_down_sync(0xffffffffu, s,  o);
        ss += __shfl_down_sync(0xffffffffu, ss, o);
    }
    int lane = threadIdx.x & 31, w = threadIdx.x >> 5, nw = blockDim.x >> 5;
    if (lane == 0) { shs[w] = s; shss[w] = ss; }
    __syncthreads();
    if (w == 0) {
        s  = (lane < nw) ? shs[lane]  : 0.f;
        ss = (lane < nw) ? shss[lane] : 0.f;
        #pragma unroll
        for (int o = 16; o > 0; o >>= 1) {
            s  += __shfl_down_sync(0xffffffffu, s,  o);
            ss += __shfl_down_sync(0xffffffffu, ss, o);
        }
        if (lane == 0) { shs[0] = s; shss[0] = ss; }
    }
    __syncthreads();
    s = shs[0]; ss = shss[0];
}

__device__ __forceinline__ float sigm(float x) { return 1.f / (1.f + expf(-x)); }

// ---------------- K0: weight transpose + bf16 split --------------------------
template <int WHICH>
__global__ void k_wsplit(const float* __restrict__ W) {
    const int N = (WHICH == 0) ? N1c : N2c;
    __nv_bfloat16* Whi = (WHICH == 0) ? wt1_hi : wt2_hi;
    __nv_bfloat16* Wlo = (WHICH == 0) ? wt1_lo : wt2_lo;
    int idx = blockIdx.x * 256 + threadIdx.x;
    int total = Hn * K1c * N;
    if (idx >= total) return;
    int h = idx / (K1c * N);
    int r = idx - h * K1c * N;
    int k = r / N, n = r - k * N;
    __nv_bfloat16 hi, lo;
    bsplit(W[idx], hi, lo);
    size_t o = ((size_t)h * N + n) * K1c + k;
    Whi[o] = hi;
    Wlo[o] = lo;
}

// ---------------- K1: exclusive cumsum over S (chunked) ----------------------
__global__ void k_chunksum(const float* __restrict__ in) {
    int blk = blockIdx.x;
    int n = blk % Hn; int c = (blk / Hn) % NC; int b = blk / (Hn * NC);
    int d = threadIdx.x;
    size_t base = ((size_t)(b * Ssz + c * LC) * Hn + n) * DIc + d;
    float s = 0.f;
    #pragma unroll 4
    for (int i = 0; i < LC; i++) s += in[base + (size_t)i * Hn * DIc];
    buf_chunk[((b * NC + c) * Hn + n) * DIc + d] = s;
}

__global__ void k_chunkscan() {
    int n = blockIdx.x % Hn, b = blockIdx.x / Hn;
    int d = threadIdx.x;
    float run = 0.f;
    for (int c = 0; c < NC; c++) {
        int idx = ((b * NC + c) * Hn + n) * DIc + d;
        float t = buf_chunk[idx];
        buf_chunk[idx] = run;
        run += t;
    }
}

__global__ void k_csum(const float* __restrict__ in) {
    int blk = blockIdx.x;
    int n = blk % Hn; int c = (blk / Hn) % NC; int b = blk / (Hn * NC);
    int d = threadIdx.x;
    float run = buf_chunk[((b * NC + c) * Hn + n) * DIc + d];
    size_t base = ((size_t)(b * Ssz + c * LC) * Hn + n) * DIc + d;
    for (int i = 0; i < LC; i++) {
        size_t p = base + (size_t)i * Hn * DIc;
        buf_csum[p] = run;
        run += in[p];
    }
}

// ---------------- K2: token LN of csum + assemble x = [input, ln(csum)] ------
__global__ void k_lnx(const float* __restrict__ in,
                      const float* __restrict__ gc, const float* __restrict__ bc) {
    int t = blockIdx.x;
    int tid = threadIdx.x;            // 256
    const float* cs = buf_csum + (size_t)t * (Hn * DIc);
    float s = 0.f, ss = 0.f;
    #pragma unroll
    for (int i = tid; i < Hn * DIc; i += 256) { float v = cs[i]; s += v; ss += v * v; }
    block_reduce2(s, ss);
    float mu = s * (1.f / (Hn * DIc));
    float var = ss * (1.f / (Hn * DIc)) - mu * mu;
    float rs = rsqrtf(var + EPSf);
    __nv_bfloat16* xh = buf_xh + (size_t)t * (Hn * K1c);
    __nv_bfloat16* xl = buf_xl + (size_t)t * (Hn * K1c);
    const float* ip = in + (size_t)t * (Hn * DIc);
    #pragma unroll
    for (int i = tid; i < Hn * DIc; i += 256) {
        int n = i >> 7, d = i & 127;
        __nv_bfloat16 hi, lo;
        bsplit(ip[i], hi, lo);
        xh[n * K1c + d] = hi; xl[n * K1c + d] = lo;
        bsplit((cs[i] - mu) * rs * gc[i] + bc[i], hi, lo);
        xh[n * K1c + 128 + d] = hi; xl[n * K1c + 128 + d] = lo;
    }
}

// ---------------- split-bf16 mma.sync GEMM -----------------------------------
// Block tile 128x128, K-stage 64, 2-stage cp.async double buffer.
// 8 warps: (w&3) -> m-group of 32, (w>>2) -> n-group of 64.
// 3 products: AhiBhi + AhiBlo + AloBhi, fp32 accum.
#define GEMM_SMEM_BYTES (2 * 4 * 16384)   // 2 stages x {Ah,Al,Bh,Bl} x 16KB = 128KB

template <int NTOT, int WHICH>
__global__ void __launch_bounds__(256, 1) k_gemm_mma(const float* __restrict__ bias) {
    const __nv_bfloat16* Ah = WHICH ? buf_x2h : buf_xh;
    const __nv_bfloat16* Al = WHICH ? buf_x2l : buf_xl;
    const __nv_bfloat16* Bh = WHICH ? wt2_hi  : wt1_hi;
    const __nv_bfloat16* Bl = WHICH ? wt2_lo  : wt1_lo;
    float* Y = WHICH ? buf_og : buf_h3;

    extern __shared__ char smch[];
    const uint32_t sbase = smem_u32(smch);

    const int tid = threadIdx.x;
    const int h  = blockIdx.z;
    const int m0 = blockIdx.y * 128;
    const int n0 = blockIdx.x * 128;
    const int w = tid >> 5, lane = tid & 31;
    const int wm = w & 3, wn = w >> 2;

    float acc[2][8][4];
    #pragma unroll
    for (int i = 0; i < 2; i++)
        #pragma unroll
        for (int j = 0; j < 8; j++)
            #pragma unroll
            for (int q = 0; q < 4; q++) acc[i][j][q] = 0.f;

    auto stage = [&](int kt, int st) {
        const uint32_t sb = sbase + st * 65536;
        const int kb = kt * 64;
        #pragma unroll
        for (int g = 0; g < 4; g++) {
            int idx = tid + 256 * g;
            int row = idx >> 3, c = idx & 7;
            uint32_t soff = (uint32_t)(row * 128 + ((c ^ (row & 7)) << 4));
            size_t ga = ((size_t)(m0 + row) * Hn + h) * K1c + kb + c * 8;
            CPA16(sb + soff,         Ah + ga);
            CPA16(sb + 16384 + soff, Al + ga);
            size_t gb = ((size_t)h * NTOT + n0 + row) * K1c + kb + c * 8;
            CPA16(sb + 32768 + soff, Bh + gb);
            CPA16(sb + 49152 + soff, Bl + gb);
        }
    };

    // per-lane ldmatrix row/parity precompute
    const int lrow = lane & 15;          // row within 16
    const int lhv  = lane >> 4;          // 16B parity (0/1)

    stage(0, 0);
    CPA_COMMIT;

    for (int kt = 0; kt < 4; kt++) {
        const int st = kt & 1;
        const uint32_t sb = sbase + st * 65536;
        CPA_WAIT0;
        __syncthreads();
        if (kt < 3) { stage(kt + 1, st ^ 1); CPA_COMMIT; }

        #pragma unroll
        for (int s = 0; s < 4; s++) {
            // A fragments (hi, lo): two m16 tiles
            uint32_t ah[2][4], al[2][4];
            #pragma unroll
            for (int im = 0; im < 2; im++) {
                int row = wm * 32 + im * 16 + lrow;
                int ch  = (s * 2 + lhv) ^ (row & 7);
                uint32_t ad = sb + (uint32_t)(row * 128 + (ch << 4));
                LDSM_X4(ah[im][0], ah[im][1], ah[im][2], ah[im][3], ad);
                LDSM_X4(al[im][0], al[im][1], al[im][2], al[im][3], ad + 16384);
            }
            // B fragments (hi, lo): 8 n8 tiles; K-major [n][k] -> NON-trans ldmatrix
            uint32_t bh[8][2], bl[8][2];
            #pragma unroll
            for (int jn = 0; jn < 4; jn++) {
                int row = wn * 64 + jn * 16 + lrow;
                int ch  = (s * 2 + lhv) ^ (row & 7);
                uint32_t ad = sb + 32768 + (uint32_t)(row * 128 + (ch << 4));
                uint32_t r0, r1, r2, r3;
                LDSM_X4(r0, r1, r2, r3, ad);
                bh[2 * jn][0] = r0; bh[2 * jn][1] = r2;
                bh[2 * jn + 1][0] = r1; bh[2 * jn + 1][1] = r3;
                LDSM_X4(r0, r1, r2, r3, ad + 16384);
                bl[2 * jn][0] = r0; bl[2 * jn][1] = r2;
                bl[2 * jn + 1][0] = r1; bl[2 * jn + 1][1] = r3;
            }
            #pragma unroll
            for (int im = 0; im < 2; im++)
                #pragma unroll
                for (int jn = 0; jn < 8; jn++) {
                    MMA16816(acc[im][jn], ah[im], bh[jn]);
                    MMA16816(acc[im][jn], ah[im], bl[jn]);
                    MMA16816(acc[im][jn], al[im], bh[jn]);
                }
        }
        __syncthreads();
    }

    // epilogue: bias add + store
    const int gr = lane >> 2, gc = (lane & 3) * 2;
    #pragma unroll
    for (int im = 0; im < 2; im++) {
        #pragma unroll
        for (int jn = 0; jn < 8; jn++) {
            int row = m0 + wm * 32 + im * 16 + gr;
            int col = n0 + wn * 64 + jn * 8 + gc;
            float2 bb = *(const float2*)(bias + h * NTOT + col);
            float* y0 = Y + ((size_t)row * Hn + h) * NTOT + col;
            y0[0] = acc[im][jn][0] + bb.x;
            y0[1] = acc[im][jn][1] + bb.y;
            float* y1 = Y + ((size_t)(row + 8) * Hn + h) * NTOT + col;
            y1[0] = acc[im][jn][2] + bb.x;
            y1[1] = acc[im][jn][3] + bb.y;
        }
    }
}

// ---------------- K4: token LN of h3 (3072 vals) + gates ---------------------
__global__ void k_gates(const float* __restrict__ gh, const float* __restrict__ bh) {
    int t = blockIdx.x;
    int d = threadIdx.x;              // 128
    const float* h = buf_h3 + (size_t)t * (Hn * N1c);
    float v[24];
    float s = 0.f, ss = 0.f;
    #pragma unroll
    for (int n = 0; n < Hn; n++)
        #pragma unroll
        for (int g = 0; g < 3; g++) {
            float x = h[n * N1c + g * 128 + d];
            v[n * 3 + g] = x; s += x; ss += x * x;
        }
    block_reduce2(s, ss);
    float mu  = s * (1.f / 3072.f);
    float var = ss * (1.f / 3072.f) - mu * mu;
    float rs  = rsqrtf(var + EPSf);
    #pragma unroll
    for (int n = 0; n < Hn; n++) {
        float ig = (v[n * 3 + 0] - mu) * rs * gh[(n * 3 + 0) * 128 + d] + bh[(n * 3 + 0) * 128 + d];
        float fv = (v[n * 3 + 1] - mu) * rs * gh[(n * 3 + 1) * 128 + d] + bh[(n * 3 + 1) * 128 + d];
        float hv = (v[n * 3 + 2] - mu) * rs * gh[(n * 3 + 2) * 128 + d] + bh[(n * 3 + 2) * 128 + d];
        size_t o = (size_t)t * (Hn * DOc) + n * DOc + d;
        buf_fg[o]  = sigm(fv);
        buf_igh[o] = sigm(ig) * fmaxf(hv, 0.f);
    }
}

// ---------------- K5: chunked linear-recurrence scan -------------------------
__global__ void k_scanA() {
    int blk = blockIdx.x;
    int n = blk % Hn; int c = (blk / Hn) % NC; int b = blk / (Hn * NC);
    int d = threadIdx.x;
    size_t base = ((size_t)(b * Ssz + c * LC) * Hn + n) * DOc + d;
    float F = 1.f, I = 0.f;
    #pragma unroll 4
    for (int i = 0; i < LC; i++) {
        size_t p = base + (size_t)i * Hn * DOc;
        float f = buf_fg[p], x = buf_igh[p];
        F *= f; I = f * I + x;
    }
    int ci = ((b * NC + c) * Hn + n) * DOc + d;
    buf_Fc[ci] = F; buf_Ic[ci] = I;
}

__global__ void k_scanB(const float* __restrict__ init_cx) {
    int n = blockIdx.x % Hn, b = blockIdx.x / Hn;
    int d = threadIdx.x;
    float c0 = init_cx[n * DOc + d];
    for (int c = 0; c < NC; c++) {
        int idx = ((b * NC + c) * Hn + n) * DOc + d;
        buf_cst[idx] = c0;
        c0 = buf_Fc[idx] * c0 + buf_Ic[idx];
    }
}

__global__ void k_scanC(const float* __restrict__ in) {
    int blk = blockIdx.x;
    int n = blk % Hn; int c = (blk / Hn) % NC; int b = blk / (Hn * NC);
    int d = threadIdx.x;
    float cc = buf_cst[((b * NC + c) * Hn + n) * DOc + d];
    size_t base = ((size_t)(b * Ssz + c * LC) * Hn + n) * DOc + d;
    for (int i = 0; i < LC; i++) {
        size_t p = base + (size_t)i * Hn * DOc;
        cc = buf_fg[p] * cc + buf_igh[p];
        int t = b * Ssz + c * LC + i;
        size_t xb = (size_t)t * (Hn * K1c) + n * K1c + d;
        __nv_bfloat16 hi, lo;
        bsplit(in[((size_t)t * Hn + n) * DIc + d], hi, lo);
        buf_x2h[xb] = hi; buf_x2l[xb] = lo;
        bsplit(cc, hi, lo);
        buf_x2h[xb + 128] = hi; buf_x2l[xb + 128] = lo;   // cell
    }
}

// ---------------- K7: token LN of og (1024) + sigmoid * cell -----------------
__global__ void k_out(const float* __restrict__ gg, const float* __restrict__ bg,
                      float* __restrict__ out) {
    int t = blockIdx.x;
    int tid = threadIdx.x;            // 256
    const float* o = buf_og + (size_t)t * (Hn * DOc);
    float s = 0.f, ss = 0.f;
    #pragma unroll
    for (int i = tid; i < Hn * DOc; i += 256) { float v = o[i]; s += v; ss += v * v; }
    block_reduce2(s, ss);
    float mu  = s * (1.f / 1024.f);
    float var = ss * (1.f / 1024.f) - mu * mu;
    float rs  = rsqrtf(var + EPSf);
    #pragma unroll
    for (int i = tid; i < Hn * DOc; i += 256) {
        int n = i >> 7, d = i & 127;
        float v = (o[i] - mu) * rs * gg[i] + bg[i];
        size_t xb = (size_t)t * (Hn * K1c) + n * K1c + 128 + d;
        float cell = __bfloat162float(buf_x2h[xb]) + __bfloat162float(buf_x2l[xb]);
        out[(size_t)t * (Hn * DOc) + i] = cell * sigm(v);
    }
}

// ---------------- launch ------------------------------------------------------
extern "C" void kernel_launch(void* const* d_in, const int* in_sizes, int n_in,
                              void* d_out, int out_size) {
    const float* heads_input = (const float*)d_in[0];
    const float* W_hid       = (const float*)d_in[1];
    const float* b_hid       = (const float*)d_in[2];
    const float* g_csum      = (const float*)d_in[3];
    const float* beta_csum   = (const float*)d_in[4];
    const float* g_hid       = (const float*)d_in[5];
    const float* beta_hid    = (const float*)d_in[6];
    const float* W_og        = (const float*)d_in[7];
    const float* b_og        = (const float*)d_in[8];
    const float* g_og        = (const float*)d_in[9];
    const float* beta_og     = (const float*)d_in[10];
    const float* init_cx     = (const float*)d_in[11];
    float* out = (float*)d_out;

    cudaFuncSetAttribute(k_gemm_mma<N1c, 0>,
        cudaFuncAttributeMaxDynamicSharedMemorySize, GEMM_SMEM_BYTES);
    cudaFuncSetAttribute(k_gemm_mma<N2c, 1>,
        cudaFuncAttributeMaxDynamicSharedMemorySize, GEMM_SMEM_BYTES);

    // 0) weight transpose + bf16 split
    k_wsplit<0><<<(Hn * K1c * N1c + 255) / 256, 256>>>(W_hid);
    k_wsplit<1><<<(Hn * K1c * N2c + 255) / 256, 256>>>(W_og);
    // 1) exclusive cumsum over S
    k_chunksum<<<Bsz * NC * Hn, 128>>>(heads_input);
    k_chunkscan<<<Bsz * Hn, 128>>>();
    k_csum<<<Bsz * NC * Hn, 128>>>(heads_input);
    // 2) token LN(csum) + build x (bf16 hi/lo)
    k_lnx<<<Tsz, 256>>>(heads_input, g_csum, beta_csum);
    // 3) GEMM1 (split-bf16 mma.sync): per-head (16384 x 384 x 256)
    k_gemm_mma<N1c, 0><<<dim3(N1c / 128, Tsz / 128, Hn), 256, GEMM_SMEM_BYTES>>>(b_hid);
    // 4) LN + gates
    k_gates<<<Tsz, 128>>>(g_hid, beta_hid);
    // 5) cell scan (chunked)
    k_scanA<<<Bsz * NC * Hn, 128>>>();
    k_scanB<<<Bsz * Hn, 128>>>(init_cx);
    k_scanC<<<Bsz * NC * Hn, 128>>>(heads_input);
    // 6) GEMM2 (split-bf16 mma.sync): per-head (16384 x 128 x 256)
    k_gemm_mma<N2c, 1><<<dim3(N2c / 128, Tsz / 128, Hn), 256, GEMM_SMEM_BYTES>>>(b_og);
    // 7) final LN + sigmoid*cell
    k_out<<<Tsz, 256>>>(g_og, beta_og, out);
}

// round 11
// speedup vs baseline: 1.5880x; 1.0954x over previous
#include <cuda_runtime.h>
#include <cuda_bf16.h>
#include <math.h>
#include <cstdint>

// Problem constants
#define Bsz 4
#define Ssz 4096
#define Hn  8
#define DIc 128
#define DOc 128
#define Tsz (Bsz*Ssz)        // 16384 tokens
#define K1c 256              // 2*DI
#define N1c 384              // 3*DO
#define N2c 128
#define NC  64               // scan chunks
#define LC  (Ssz/NC)         // 64 steps per chunk
#define EPSf 1e-6f

// ---------------- static scratch (device globals; no allocation) -------------
__device__ float buf_csum[(size_t)Tsz*Hn*DIc];
__device__ __align__(16) __nv_bfloat16 buf_xh [(size_t)Tsz*Hn*K1c];  // A1 hi
__device__ __align__(16) __nv_bfloat16 buf_xl [(size_t)Tsz*Hn*K1c];  // A1 lo
__device__ __align__(16) __nv_bfloat16 buf_x2h[(size_t)Tsz*Hn*K1c];  // A2 hi
__device__ __align__(16) __nv_bfloat16 buf_x2l[(size_t)Tsz*Hn*K1c];  // A2 lo
__device__ float buf_h3  [(size_t)Tsz*Hn*N1c];
__device__ float buf_fg  [(size_t)Tsz*Hn*DOc];
__device__ float buf_igh [(size_t)Tsz*Hn*DOc];
__device__ float buf_og  [(size_t)Tsz*Hn*DOc];
__device__ float buf_chunk[Bsz*NC*Hn*DIc];
__device__ float buf_Fc  [Bsz*NC*Hn*DOc];
__device__ float buf_Ic  [Bsz*NC*Hn*DOc];
__device__ float buf_cst [Bsz*NC*Hn*DOc];
// pre-split / transposed weights: [h][n][k] bf16 hi/lo
__device__ __align__(16) __nv_bfloat16 wt1_hi[(size_t)Hn*N1c*K1c];
__device__ __align__(16) __nv_bfloat16 wt1_lo[(size_t)Hn*N1c*K1c];
__device__ __align__(16) __nv_bfloat16 wt2_hi[(size_t)Hn*N2c*K1c];
__device__ __align__(16) __nv_bfloat16 wt2_lo[(size_t)Hn*N2c*K1c];

// ---------------- PTX helpers -------------------------------------------------
__device__ __forceinline__ uint32_t smem_u32(const void* p) {
    uint32_t a;
    asm("{ .reg .u64 t; cvta.to.shared.u64 t, %1; cvt.u32.u64 %0, t; }" : "=r"(a) : "l"(p));
    return a;
}
#define CPA16(sm_addr, gm_ptr) \
    asm volatile("cp.async.cg.shared.global [%0], [%1], 16;" \
                 :: "r"(sm_addr), "l"(gm_ptr) : "memory")
#define CPA_COMMIT asm volatile("cp.async.commit_group;" ::: "memory")
#define CPA_WAIT0  asm volatile("cp.async.wait_group 0;"  ::: "memory")

#define LDSM_X4(r0,r1,r2,r3,addr) \
    asm volatile("ldmatrix.sync.aligned.m8n8.x4.shared.b16 {%0,%1,%2,%3},[%4];" \
                 : "=r"(r0),"=r"(r1),"=r"(r2),"=r"(r3) : "r"(addr))

#define MMA16816(d, a, b) \
    asm volatile("mma.sync.aligned.m16n8k16.row.col.f32.bf16.bf16.f32 " \
                 "{%0,%1,%2,%3},{%4,%5,%6,%7},{%8,%9},{%0,%1,%2,%3};" \
                 : "+f"((d)[0]),"+f"((d)[1]),"+f"((d)[2]),"+f"((d)[3]) \
                 : "r"((a)[0]),"r"((a)[1]),"r"((a)[2]),"r"((a)[3]), \
                   "r"((b)[0]),"r"((b)[1]))

__device__ __forceinline__ void bsplit(float v, __nv_bfloat16& hi, __nv_bfloat16& lo) {
    hi = __float2bfloat16_rn(v);
    lo = __float2bfloat16_rn(v - __bfloat162float(hi));
}
// split float4 -> two packed uint2 (4 bf16 each)
__device__ __forceinline__ void bsplit4(float4 v, uint2& hi, uint2& lo) {
    __nv_bfloat16 h0,l0,h1,l1,h2,l2,h3,l3;
    bsplit(v.x,h0,l0); bsplit(v.y,h1,l1); bsplit(v.z,h2,l2); bsplit(v.w,h3,l3);
    hi.x = (uint32_t)__bfloat16_as_ushort(h0) | ((uint32_t)__bfloat16_as_ushort(h1) << 16);
    hi.y = (uint32_t)__bfloat16_as_ushort(h2) | ((uint32_t)__bfloat16_as_ushort(h3) << 16);
    lo.x = (uint32_t)__bfloat16_as_ushort(l0) | ((uint32_t)__bfloat16_as_ushort(l1) << 16);
    lo.y = (uint32_t)__bfloat16_as_ushort(l2) | ((uint32_t)__bfloat16_as_ushort(l3) << 16);
}
__device__ __forceinline__ float4 bunpack4(uint2 h, uint2 l) {
    float4 r;
    r.x = __bfloat162float(__ushort_as_bfloat16((unsigned short)(h.x & 0xffff)))
        + __bfloat162float(__ushort_as_bfloat16((unsigned short)(l.x & 0xffff)));
    r.y = __bfloat162float(__ushort_as_bfloat16((unsigned short)(h.x >> 16)))
        + __bfloat162float(__ushort_as_bfloat16((unsigned short)(l.x >> 16)));
    r.z = __bfloat162float(__ushort_as_bfloat16((unsigned short)(h.y & 0xffff)))
        + __bfloat162float(__ushort_as_bfloat16((unsigned short)(l.y & 0xffff)));
    r.w = __bfloat162float(__ushort_as_bfloat16((unsigned short)(h.y >> 16)))
        + __bfloat162float(__ushort_as_bfloat16((unsigned short)(l.y >> 16)));
    return r;
}
__device__ __forceinline__ float4 ld4(const float* p) { return *(const float4*)p; }
__device__ __forceinline__ void st4(float* p, float4 v) { *(float4*)p = v; }

// ---------------- helpers ----------------------------------------------------
__device__ __forceinline__ void block_reduce2(float& s, float& ss) {
    __shared__ float shs[32], shss[32];
    #pragma unroll
    for (int o = 16; o > 0; o >>= 1) {
        s  += __shfl_down_sync(0xffffffffu, s,  o);
        ss += __shfl_down_sync(0xffffffffu, ss, o);
    }
    int lane = threadIdx.x & 31, w = threadIdx.x >> 5, nw = blockDim.x >> 5;
    if (lane == 0) { shs[w] = s; shss[w] = ss; }
    __syncthreads();
    if (w == 0) {
        s  = (lane < nw) ? shs[lane]  : 0.f;
        ss = (lane < nw) ? shss[lane] : 0.f;
        #pragma unroll
        for (int o = 16; o > 0; o >>= 1) {
            s  += __shfl_down_sync(0xffffffffu, s,  o);
            ss += __shfl_down_sync(0xffffffffu, ss, o);
        }
        if (lane == 0) { shs[0] = s; shss[0] = ss; }
    }
    __syncthreads();
    s = shs[0]; ss = shss[0];
}

__device__ __forceinline__ float sigm(float x) { return 1.f / (1.f + expf(-x)); }

// ---------------- K0: weight transpose + bf16 split (smem tiled) -------------
template <int WHICH>
__global__ void k_wsplit(const float* __restrict__ W) {
    const int N = (WHICH == 0) ? N1c : N2c;
    __nv_bfloat16* Whi = (WHICH == 0) ? wt1_hi : wt2_hi;
    __nv_bfloat16* Wlo = (WHICH == 0) ? wt1_lo : wt2_lo;
    __shared__ float tile[32][33];
    const int n0 = blockIdx.x * 32, k0 = blockIdx.y * 32, hh = blockIdx.z;
    const int tid = threadIdx.x;
    // load 32 k-rows x 32 n-cols (coalesced float4 along n)
    {
        int r = tid >> 3, cq = tid & 7;
        float4 v = ld4(W + ((size_t)hh * K1c + k0 + r) * N + n0 + cq * 4);
        tile[r][cq * 4 + 0] = v.x; tile[r][cq * 4 + 1] = v.y;
        tile[r][cq * 4 + 2] = v.z; tile[r][cq * 4 + 3] = v.w;
    }
    __syncthreads();
    // write transposed: [h][n][k], coalesced 8B along k
    {
        int nr = tid >> 3, kq = tid & 7;
        float4 v;
        v.x = tile[kq * 4 + 0][nr]; v.y = tile[kq * 4 + 1][nr];
        v.z = tile[kq * 4 + 2][nr]; v.w = tile[kq * 4 + 3][nr];
        uint2 hi, lo;
        bsplit4(v, hi, lo);
        size_t o = ((size_t)hh * N + n0 + nr) * K1c + k0 + kq * 4;
        *(uint2*)(Whi + o) = hi;
        *(uint2*)(Wlo + o) = lo;
    }
}

// ---------------- K1: exclusive cumsum over S (chunked, float4) --------------
__global__ void k_chunksum(const float* __restrict__ in) {
    int blk = blockIdx.x;                       // b*NC + c
    int b = blk / NC, c = blk % NC;
    int q4 = threadIdx.x * 4;                   // 0..1023
    size_t t0 = (size_t)(b * Ssz + c * LC);
    float4 s = make_float4(0.f, 0.f, 0.f, 0.f);
    #pragma unroll 4
    for (int i = 0; i < LC; i++) {
        float4 v = ld4(in + ((t0 + i) << 10) + q4);
        s.x += v.x; s.y += v.y; s.z += v.z; s.w += v.w;
    }
    st4(buf_chunk + ((size_t)blk << 10) + q4, s);
}

__global__ void k_chunkscan() {
    int b = blockIdx.x;
    int q4 = threadIdx.x * 4;
    float4 run = make_float4(0.f, 0.f, 0.f, 0.f);
    for (int c = 0; c < NC; c++) {
        size_t idx = ((size_t)(b * NC + c) << 10) + q4;
        float4 t = ld4(buf_chunk + idx);
        st4(buf_chunk + idx, run);
        run.x += t.x; run.y += t.y; run.z += t.z; run.w += t.w;
    }
}

__global__ void k_csum(const float* __restrict__ in) {
    int blk = blockIdx.x;
    int b = blk / NC, c = blk % NC;
    int q4 = threadIdx.x * 4;
    size_t t0 = (size_t)(b * Ssz + c * LC);
    float4 run = ld4(buf_chunk + ((size_t)blk << 10) + q4);
    for (int i = 0; i < LC; i++) {
        size_t p = ((t0 + i) << 10) + q4;
        st4(buf_csum + p, run);
        float4 v = ld4(in + p);
        run.x += v.x; run.y += v.y; run.z += v.z; run.w += v.w;
    }
}

// ---------------- K2: token LN of csum + assemble x (float4) -----------------
__global__ void k_lnx(const float* __restrict__ in,
                      const float* __restrict__ gc, const float* __restrict__ bc) {
    int t = blockIdx.x;
    int i = threadIdx.x * 4;          // 0..1023
    float4 cs = ld4(buf_csum + ((size_t)t << 10) + i);
    float4 ip = ld4(in + ((size_t)t << 10) + i);
    float s  = cs.x + cs.y + cs.z + cs.w;
    float ss = cs.x * cs.x + cs.y * cs.y + cs.z * cs.z + cs.w * cs.w;
    block_reduce2(s, ss);
    float mu = s * (1.f / 1024.f);
    float var = ss * (1.f / 1024.f) - mu * mu;
    float rs = rsqrtf(var + EPSf);
    float4 g4 = ld4(gc + i), b4 = ld4(bc + i);
    float4 ln;
    ln.x = (cs.x - mu) * rs * g4.x + b4.x;
    ln.y = (cs.y - mu) * rs * g4.y + b4.y;
    ln.z = (cs.z - mu) * rs * g4.z + b4.z;
    ln.w = (cs.w - mu) * rs * g4.w + b4.w;
    int n = i >> 7, d = i & 127;
    size_t xb = ((size_t)t << 11) + n * K1c + d;
    uint2 hi, lo;
    bsplit4(ip, hi, lo);
    *(uint2*)(buf_xh + xb) = hi; *(uint2*)(buf_xl + xb) = lo;
    bsplit4(ln, hi, lo);
    *(uint2*)(buf_xh + xb + 128) = hi; *(uint2*)(buf_xl + xb + 128) = lo;
}

// ---------------- split-bf16 mma.sync GEMM -----------------------------------
// Block tile 128x128, K-stage 32, 2-stage cp.async double buffer.
// 80B padded row stride (5*row+chunk mod 8 -> conflict-free ldmatrix).
// 2 CTAs/SM (80KB smem per CTA).
#define STG_BUF   10240                // 128 rows x 80B
#define STG_BYTES (4 * STG_BUF)        // Ah,Al,Bh,Bl
#define GEMM_SMEM_BYTES (2 * STG_BYTES)

template <int NTOT, int WHICH>
__global__ void __launch_bounds__(256, 2) k_gemm_mma(const float* __restrict__ bias) {
    const __nv_bfloat16* Ah = WHICH ? buf_x2h : buf_xh;
    const __nv_bfloat16* Al = WHICH ? buf_x2l : buf_xl;
    const __nv_bfloat16* Bh = WHICH ? wt2_hi  : wt1_hi;
    const __nv_bfloat16* Bl = WHICH ? wt2_lo  : wt1_lo;
    float* Y = WHICH ? buf_og : buf_h3;

    extern __shared__ char smch[];
    const uint32_t sbase = smem_u32(smch);

    const int tid = threadIdx.x;
    const int h  = blockIdx.z;
    const int m0 = blockIdx.y * 128;
    const int n0 = blockIdx.x * 128;
    const int w = tid >> 5, lane = tid & 31;
    const int wm = w & 3, wn = w >> 2;

    float acc[2][8][4];
    #pragma unroll
    for (int i = 0; i < 2; i++)
        #pragma unroll
        for (int j = 0; j < 8; j++)
            #pragma unroll
            for (int q = 0; q < 4; q++) acc[i][j][q] = 0.f;

    auto stage = [&](int kt, int st) {
        const uint32_t sb = sbase + st * STG_BYTES;
        const int kb = kt * 32;
        #pragma unroll
        for (int g = 0; g < 2; g++) {
            int idx = tid + 256 * g;
            int row = idx >> 2, c = idx & 3;
            uint32_t soff = (uint32_t)(row * 80 + c * 16);
            size_t ga = ((size_t)(m0 + row) * Hn + h) * K1c + kb + c * 8;
            CPA16(sb + soff,               Ah + ga);
            CPA16(sb + STG_BUF + soff,     Al + ga);
            size_t gb = ((size_t)h * NTOT + n0 + row) * K1c + kb + c * 8;
            CPA16(sb + 2 * STG_BUF + soff, Bh + gb);
            CPA16(sb + 3 * STG_BUF + soff, Bl + gb);
        }
    };

    const int lrow = lane & 15;          // row within 16
    const int lhv  = lane >> 4;          // 16B parity (0/1)

    stage(0, 0);
    CPA_COMMIT;

    for (int kt = 0; kt < 8; kt++) {
        const int st = kt & 1;
        const uint32_t sb = sbase + st * STG_BYTES;
        CPA_WAIT0;
        __syncthreads();
        if (kt < 7) { stage(kt + 1, st ^ 1); CPA_COMMIT; }

        #pragma unroll
        for (int s = 0; s < 2; s++) {
            const int ch = s * 2 + lhv;   // 16B chunk 0..3
            // A fragments (hi, lo): two m16 tiles
            uint32_t ah[2][4], al[2][4];
            #pragma unroll
            for (int im = 0; im < 2; im++) {
                int row = wm * 32 + im * 16 + lrow;
                uint32_t ad = sb + (uint32_t)(row * 80 + (ch << 4));
                LDSM_X4(ah[im][0], ah[im][1], ah[im][2], ah[im][3], ad);
                LDSM_X4(al[im][0], al[im][1], al[im][2], al[im][3], ad + STG_BUF);
            }
            // B fragments (hi, lo): 8 n8 tiles; K-major [n][k] -> non-trans ldmatrix
            uint32_t bh[8][2], bl[8][2];
            #pragma unroll
            for (int jn = 0; jn < 4; jn++) {
                int row = wn * 64 + jn * 16 + lrow;
                uint32_t ad = sb + 2 * STG_BUF + (uint32_t)(row * 80 + (ch << 4));
                uint32_t r0, r1, r2, r3;
                LDSM_X4(r0, r1, r2, r3, ad);
                bh[2 * jn][0] = r0; bh[2 * jn][1] = r2;
                bh[2 * jn + 1][0] = r1; bh[2 * jn + 1][1] = r3;
                LDSM_X4(r0, r1, r2, r3, ad + STG_BUF);
                bl[2 * jn][0] = r0; bl[2 * jn][1] = r2;
                bl[2 * jn + 1][0] = r1; bl[2 * jn + 1][1] = r3;
            }
            #pragma unroll
            for (int im = 0; im < 2; im++)
                #pragma unroll
                for (int jn = 0; jn < 8; jn++) {
                    MMA16816(acc[im][jn], ah[im], bh[jn]);
                    MMA16816(acc[im][jn], ah[im], bl[jn]);
                    MMA16816(acc[im][jn], al[im], bh[jn]);
                }
        }
        __syncthreads();
    }

    // epilogue: bias add + store
    const int gr = lane >> 2, gc = (lane & 3) * 2;
    #pragma unroll
    for (int im = 0; im < 2; im++) {
        #pragma unroll
        for (int jn = 0; jn < 8; jn++) {
            int row = m0 + wm * 32 + im * 16 + gr;
            int col = n0 + wn * 64 + jn * 8 + gc;
            float2 bb = *(const float2*)(bias + h * NTOT + col);
            float* y0 = Y + ((size_t)row * Hn + h) * NTOT + col;
            y0[0] = acc[im][jn][0] + bb.x;
            y0[1] = acc[im][jn][1] + bb.y;
            float* y1 = Y + ((size_t)(row + 8) * Hn + h) * NTOT + col;
            y1[0] = acc[im][jn][2] + bb.x;
            y1[1] = acc[im][jn][3] + bb.y;
        }
    }
}

// ---------------- K4: token LN of h3 (3072 vals) + gates (float4) ------------
__global__ void k_gates(const float* __restrict__ gh, const float* __restrict__ bh) {
    int t = blockIdx.x;
    int tid = threadIdx.x;              // 128
    const float* hp = buf_h3 + (size_t)t * (Hn * N1c);
    float4 v[2][3];
    float s = 0.f, ss = 0.f;
    #pragma unroll
    for (int r = 0; r < 2; r++) {
        int qq = tid + 128 * r;          // 0..255 quad index
        int n = qq >> 5, d = (qq & 31) * 4;
        #pragma unroll
        for (int g = 0; g < 3; g++) {
            float4 x = ld4(hp + n * N1c + g * 128 + d);
            v[r][g] = x;
            s  += x.x + x.y + x.z + x.w;
            ss += x.x * x.x + x.y * x.y + x.z * x.z + x.w * x.w;
        }
    }
    block_reduce2(s, ss);
    float mu  = s * (1.f / 3072.f);
    float var = ss * (1.f / 3072.f) - mu * mu;
    float rs  = rsqrtf(var + EPSf);
    #pragma unroll
    for (int r = 0; r < 2; r++) {
        int qq = tid + 128 * r;
        int n = qq >> 5, d = (qq & 31) * 4;
        float4 gv[3], bv[3];
        #pragma unroll
        for (int g = 0; g < 3; g++) {
            gv[g] = ld4(gh + (n * 3 + g) * 128 + d);
            bv[g] = ld4(bh + (n * 3 + g) * 128 + d);
        }
        float4 ig, fv4, hv4, fgv, ighv;
        ig.x = (v[r][0].x - mu) * rs * gv[0].x + bv[0].x;
        ig.y = (v[r][0].y - mu) * rs * gv[0].y + bv[0].y;
        ig.z = (v[r][0].z - mu) * rs * gv[0].z + bv[0].z;
        ig.w = (v[r][0].w - mu) * rs * gv[0].w + bv[0].w;
        fv4.x = (v[r][1].x - mu) * rs * gv[1].x + bv[1].x;
        fv4.y = (v[r][1].y - mu) * rs * gv[1].y + bv[1].y;
        fv4.z = (v[r][1].z - mu) * rs * gv[1].z + bv[1].z;
        fv4.w = (v[r][1].w - mu) * rs * gv[1].w + bv[1].w;
        hv4.x = (v[r][2].x - mu) * rs * gv[2].x + bv[2].x;
        hv4.y = (v[r][2].y - mu) * rs * gv[2].y + bv[2].y;
        hv4.z = (v[r][2].z - mu) * rs * gv[2].z + bv[2].z;
        hv4.w = (v[r][2].w - mu) * rs * gv[2].w + bv[2].w;
        fgv.x = sigm(fv4.x); fgv.y = sigm(fv4.y); fgv.z = sigm(fv4.z); fgv.w = sigm(fv4.w);
        ighv.x = sigm(ig.x) * fmaxf(hv4.x, 0.f);
        ighv.y = sigm(ig.y) * fmaxf(hv4.y, 0.f);
        ighv.z = sigm(ig.z) * fmaxf(hv4.z, 0.f);
        ighv.w = sigm(ig.w) * fmaxf(hv4.w, 0.f);
        size_t o = ((size_t)t << 10) + n * 128 + d;
        st4(buf_fg + o, fgv);
        st4(buf_igh + o, ighv);
    }
}

// ---------------- K5: chunked linear-recurrence scan (float4) ----------------
__global__ void k_scanA() {
    int blk = blockIdx.x;               // b*NC + c
    int b = blk / NC, c = blk % NC;
    int q4 = threadIdx.x * 4;
    size_t t0 = (size_t)(b * Ssz + c * LC);
    float4 F = make_float4(1.f, 1.f, 1.f, 1.f);
    float4 I = make_float4(0.f, 0.f, 0.f, 0.f);
    #pragma unroll 4
    for (int i = 0; i < LC; i++) {
        size_t p = ((t0 + i) << 10) + q4;
        float4 f = ld4(buf_fg + p), x = ld4(buf_igh + p);
        F.x *= f.x; F.y *= f.y; F.z *= f.z; F.w *= f.w;
        I.x = f.x * I.x + x.x; I.y = f.y * I.y + x.y;
        I.z = f.z * I.z + x.z; I.w = f.w * I.w + x.w;
    }
    st4(buf_Fc + ((size_t)blk << 10) + q4, F);
    st4(buf_Ic + ((size_t)blk << 10) + q4, I);
}

__global__ void k_scanB(const float* __restrict__ init_cx) {
    int b = blockIdx.x;
    int q4 = threadIdx.x * 4;
    float4 c0 = ld4(init_cx + q4);
    for (int c = 0; c < NC; c++) {
        size_t idx = ((size_t)(b * NC + c) << 10) + q4;
        st4(buf_cst + idx, c0);
        float4 F = ld4(buf_Fc + idx), I = ld4(buf_Ic + idx);
        c0.x = F.x * c0.x + I.x; c0.y = F.y * c0.y + I.y;
        c0.z = F.z * c0.z + I.z; c0.w = F.w * c0.w + I.w;
    }
}

__global__ void k_scanC(const float* __restrict__ in) {
    int blk = blockIdx.x;
    int b = blk / NC, c = blk % NC;
    int q = threadIdx.x;
    int q4 = q * 4;
    int n = q >> 5, d = (q & 31) * 4;
    size_t t0 = (size_t)(b * Ssz + c * LC);
    float4 cc = ld4(buf_cst + ((size_t)blk << 10) + q4);
    for (int i = 0; i < LC; i++) {
        size_t t = t0 + i;
        size_t p = (t << 10) + q4;
        float4 f = ld4(buf_fg + p), x = ld4(buf_igh + p);
        cc.x = f.x * cc.x + x.x; cc.y = f.y * cc.y + x.y;
        cc.z = f.z * cc.z + x.z; cc.w = f.w * cc.w + x.w;
        size_t xb = (t << 11) + n * K1c + d;
        uint2 hi, lo;
        bsplit4(ld4(in + p), hi, lo);
        *(uint2*)(buf_x2h + xb) = hi; *(uint2*)(buf_x2l + xb) = lo;
        bsplit4(cc, hi, lo);
        *(uint2*)(buf_x2h + xb + 128) = hi; *(uint2*)(buf_x2l + xb + 128) = lo;
    }
}

// ---------------- K7: token LN of og (1024) + sigmoid * cell (float4) --------
__global__ void k_out(const float* __restrict__ gg, const float* __restrict__ bg,
                      float* __restrict__ out) {
    int t = blockIdx.x;
    int i = threadIdx.x * 4;
    float4 o4 = ld4(buf_og + ((size_t)t << 10) + i);
    float s  = o4.x + o4.y + o4.z + o4.w;
    float ss = o4.x * o4.x + o4.y * o4.y + o4.z * o4.z + o4.w * o4.w;
    block_reduce2(s, ss);
    float mu  = s * (1.f / 1024.f);
    float var = ss * (1.f / 1024.f) - mu * mu;
    float rs  = rsqrtf(var + EPSf);
    float4 g4 = ld4(gg + i), b4 = ld4(bg + i);
    int n = i >> 7, d = i & 127;
    size_t xb = ((size_t)t << 11) + n * K1c + 128 + d;
    float4 cell = bunpack4(*(const uint2*)(buf_x2h + xb), *(const uint2*)(buf_x2l + xb));
    float4 r;
    r.x = cell.x * sigm((o4.x - mu) * rs * g4.x + b4.x);
    r.y = cell.y * sigm((o4.y - mu) * rs * g4.y + b4.y);
    r.z = cell.z * sigm((o4.z - mu) * rs * g4.z + b4.z);
    r.w = cell.w * sigm((o4.w - mu) * rs * g4.w + b4.w);
    st4(out + ((size_t)t << 10) + i, r);
}

// ---------------- launch ------------------------------------------------------
extern "C" void kernel_launch(void* const* d_in, const int* in_sizes, int n_in,
                              void* d_out, int out_size) {
    const float* heads_input = (const float*)d_in[0];
    const float* W_hid       = (const float*)d_in[1];
    const float* b_hid       = (const float*)d_in[2];
    const float* g_csum      = (const float*)d_in[3];
    const float* beta_csum   = (const float*)d_in[4];
    const float* g_hid       = (const float*)d_in[5];
    const float* beta_hid    = (const float*)d_in[6];
    const float* W_og        = (const float*)d_in[7];
    const float* b_og        = (const float*)d_in[8];
    const float* g_og        = (const float*)d_in[9];
    const float* beta_og     = (const float*)d_in[10];
    const float* init_cx     = (const float*)d_in[11];
    float* out = (float*)d_out;

    cudaFuncSetAttribute(k_gemm_mma<N1c, 0>,
        cudaFuncAttributeMaxDynamicSharedMemorySize, GEMM_SMEM_BYTES);
    cudaFuncSetAttribute(k_gemm_mma<N2c, 1>,
        cudaFuncAttributeMaxDynamicSharedMemorySize, GEMM_SMEM_BYTES);

    // 0) weight transpose + bf16 split (tiled)
    k_wsplit<0><<<dim3(N1c / 32, K1c / 32, Hn), 256>>>(W_hid);
    k_wsplit<1><<<dim3(N2c / 32, K1c / 32, Hn), 256>>>(W_og);
    // 1) exclusive cumsum over S
    k_chunksum<<<Bsz * NC, 256>>>(heads_input);
    k_chunkscan<<<Bsz, 256>>>();
    k_csum<<<Bsz * NC, 256>>>(heads_input);
    // 2) token LN(csum) + build x (bf16 hi/lo)
    k_lnx<<<Tsz, 256>>>(heads_input, g_csum, beta_csum);
    // 3) GEMM1 (split-bf16 mma.sync): per-head (16384 x 384 x 256)
    k_gemm_mma<N1c, 0><<<dim3(N1c / 128, Tsz / 128, Hn), 256, GEMM_SMEM_BYTES>>>(b_hid);
    // 4) LN + gates
    k_gates<<<Tsz, 128>>>(g_hid, beta_hid);
    // 5) cell scan (chunked)
    k_scanA<<<Bsz * NC, 256>>>();
    k_scanB<<<Bsz, 256>>>(init_cx);
    k_scanC<<<Bsz * NC, 256>>>(heads_input);
    // 6) GEMM2 (split-bf16 mma.sync): per-head (16384 x 128 x 256)
    k_gemm_mma<N2c, 1><<<dim3(N2c / 128, Tsz / 128, Hn), 256, GEMM_SMEM_BYTES>>>(b_og);
    // 7) final LN + sigmoid*cell
    k_out<<<Tsz, 256>>>(g_og, beta_og, out);
}